// round 4
// baseline (speedup 1.0000x reference)
#include <cuda_runtime.h>

// Problem constants
#define Bn 32
#define Cn 64
#define Hn 112
#define Wn 112
static constexpr int HW    = Hn * Wn;        // 12544
static constexpr int BHW   = Bn * HW;        // 401408
static constexpr int TOTAL = Bn * Cn * HW;   // 25690112
static constexpr float ALPHA = 0.25f;
static constexpr int PAIRS = Bn * (Hn / 2) * Wn;   // 200704 (2 vertical px/thread)

// Scratch (no cudaMalloc allowed)
__device__ unsigned long long g_bits1[BHW];
__device__ unsigned long long g_bits2[BHW];
__device__ float g_out1[TOTAL];                     // ~103 MB .bss
__device__ __align__(16) unsigned long long g_w[2][Cn][10];  // 9 words + pad
__device__ unsigned long long g_tab[2][Cn];         // packed popc-correction bytes
__device__ float4 g_par[2][Cn];                     // {ALPHA*scale, bA, aP, bB}
__device__ float g_k1[Cn];                          // b21 (stage-1 repack bias)

// ---------------------------------------------------------------------------
// K0: weight prep. scale = mean|w|; pack sign bits (w>=0 -> bit 1); build
// per-oc correction table: byte-packed popcount sums for boundary handling:
//   [0]=row0 sum  [1]=row2 sum  [2]=col0 sum  [3]=col2 sum
//   [4]=p(0,0) [5]=p(0,2) [6]=p(2,0) [7]=p(2,2)
// Also packs epilogue params {ALPHA*scale, bA, aP, bB} as float4.
// ---------------------------------------------------------------------------
__global__ void prep_weights(const float* __restrict__ w3,
                             const float* __restrict__ wpw,
                             const float* __restrict__ b12,
                             const float* __restrict__ a1,
                             const float* __restrict__ b13,
                             const float* __restrict__ b22,
                             const float* __restrict__ a2,
                             const float* __restrict__ b23,
                             const float* __restrict__ b21)
{
    int t = threadIdx.x;            // 0..127
    int set = t >> 6;               // 0 = w3, 1 = w_pw
    int oc  = t & 63;
    const float* w = set ? wpw : w3;
    float s = 0.f;
    unsigned long long wd[9];
    #pragma unroll
    for (int tap = 0; tap < 9; tap++) {
        unsigned long long word = 0ull;
        for (int ic = 0; ic < 64; ic++) {
            float v = w[(oc * 64 + ic) * 9 + tap];
            s += fabsf(v);
            word |= (unsigned long long)(v >= 0.f) << ic;
        }
        wd[tap] = word;
        g_w[set][oc][tap] = word;
    }
    g_w[set][oc][9] = 0ull;
    float scale = s * (1.f / 576.f);

    unsigned long long pc[9];
    #pragma unroll
    for (int tap = 0; tap < 9; tap++) pc[tap] = (unsigned long long)__popcll(wd[tap]);
    unsigned long long tab = 0;
    tab |= (pc[0] + pc[1] + pc[2]);         // row0
    tab |= (pc[6] + pc[7] + pc[8]) << 8;    // row2
    tab |= (pc[0] + pc[3] + pc[6]) << 16;   // col0
    tab |= (pc[2] + pc[5] + pc[8]) << 24;   // col2
    tab |= pc[0] << 32;                     // corners
    tab |= pc[2] << 40;
    tab |= pc[6] << 48;
    tab |= pc[8] << 56;
    g_tab[set][oc] = tab;

    if (set == 0) {
        g_par[0][oc] = make_float4(ALPHA * scale, b12[oc], a1[oc], b13[oc]);
        g_k1[oc] = b21[oc];
    } else {
        g_par[1][oc] = make_float4(ALPHA * scale, b22[oc], a2[oc], b23[oc]);
    }
}

// ---------------------------------------------------------------------------
// K1: pack1 — 4 pixels/thread, vectorized LDG.128 reads + STG.128 writes.
// bits1[pix] = bitpack over c of (x + b11[c] >= 0).
// ---------------------------------------------------------------------------
__global__ void pack1_kernel(const float* __restrict__ x,
                             const float* __restrict__ b11)
{
    __shared__ float sb[64];
    if (threadIdx.x < 64) sb[threadIdx.x] = b11[threadIdx.x];
    __syncthreads();

    int t = blockIdx.x * blockDim.x + threadIdx.x;
    if (t >= BHW / 4) return;
    int b = t / (HW / 4);
    int hw = (t - b * (HW / 4)) * 4;
    const float4* xp = (const float4*)(x + (size_t)b * Cn * HW + hw);

    unsigned long long w0 = 0, w1 = 0, w2 = 0, w3v = 0;
    #pragma unroll 8
    for (int c = 0; c < 64; c++) {
        float4 v = __ldg(&xp[c * (HW / 4)]);
        float bc = sb[c];
        w0  |= (unsigned long long)(v.x + bc >= 0.f) << c;
        w1  |= (unsigned long long)(v.y + bc >= 0.f) << c;
        w2  |= (unsigned long long)(v.z + bc >= 0.f) << c;
        w3v |= (unsigned long long)(v.w + bc >= 0.f) << c;
    }
    ulonglong2* dst = (ulonglong2*)(g_bits1 + (size_t)b * HW + hw);
    dst[0] = make_ulonglong2(w0, w1);
    dst[1] = make_ulonglong2(w2, w3v);
}

// ---------------------------------------------------------------------------
// Binary conv + fused epilogue. One thread = 2 vertically-adjacent pixels
// (y0, y0+1); 12-word shared neighborhood, 4-oc chunks:
//   phase 1: 8 residual LDGs (MLP 8)
//   phase 2: vectorized weight LDS (.128) + pure-ALU popcounts (no masks;
//            OOB taps over-counted then corrected via g_tab on edge threads)
//   phase 3: float epilogue + stores (+ in-register bit repack for STAGE 1)
// ---------------------------------------------------------------------------
template <int STAGE>
__device__ __forceinline__ void conv_body(const float* __restrict__ resid,
                                          float* __restrict__ outp)
{
    __shared__ __align__(16) unsigned long long sw[Cn * 10];
    __shared__ float4 spar[Cn];
    __shared__ float sK[Cn];
    __shared__ unsigned long long stab[Cn];

    const unsigned long long* gw = &g_w[STAGE - 1][0][0];
    for (int i = threadIdx.x; i < Cn * 10; i += blockDim.x) sw[i] = gw[i];
    if (threadIdx.x < 64) {
        spar[threadIdx.x] = g_par[STAGE - 1][threadIdx.x];
        stab[threadIdx.x] = g_tab[STAGE - 1][threadIdx.x];
        sK[threadIdx.x]   = (STAGE == 1) ? g_k1[threadIdx.x] : 0.f;
    }
    __syncthreads();

    int pp = blockIdx.x * blockDim.x + threadIdx.x;
    if (pp >= PAIRS) return;
    int b   = pp / (Wn * Hn / 2);
    int rem = pp - b * (Wn * Hn / 2);
    int py  = rem / Wn;
    int x   = rem - py * Wn;
    int y0  = 2 * py;

    const int t0 = (y0 == 0);
    const int bo = (y0 == Hn - 2);
    const int lf = (x == 0);
    const int rt = (x == Wn - 1);
    const bool edge = (t0 | bo | lf | rt) != 0;

    const unsigned long long* bp =
        ((STAGE == 1) ? g_bits1 : g_bits2) + (size_t)b * HW;
    const int base = y0 * Wn + x;

    // 4 rows x 3 cols neighborhood; OOB words loaded as 0 (over-count fixed later)
    unsigned long long nb[12];
    #pragma unroll
    for (int rr = 0; rr < 4; rr++) {
        bool rok = (rr == 0) ? !t0 : (rr == 3) ? !bo : true;
        int rb = base + (rr - 1) * Wn;
        nb[rr * 3 + 0] = (rok && !lf) ? bp[rb - 1] : 0ull;
        nb[rr * 3 + 1] =  rok         ? bp[rb]     : 0ull;
        nb[rr * 3 + 2] = (rok && !rt) ? bp[rb + 1] : 0ull;
    }

    const int cols  = 3 - lf - rt;
    const int base0 = 64 * (3 - t0) * cols;
    const int base1 = 64 * (3 - bo) * cols;

    const float* rp0 = resid + (size_t)b * Cn * HW + base;
    float*       op0 = outp  + (size_t)b * Cn * HW + base;

    unsigned long long pk0 = 0ull, pk1 = 0ull;

    #pragma unroll 1
    for (int c4 = 0; c4 < 16; c4++) {
        const int oc0 = c4 * 4;

        // Phase 1: batched residual loads
        float r0[4], r1[4];
        #pragma unroll
        for (int j = 0; j < 4; j++) {
            r0[j] = rp0[(oc0 + j) * HW];
            r1[j] = rp0[(oc0 + j) * HW + Wn];
        }

        // Phase 2: popcounts
        int d0[4], d1[4];
        #pragma unroll
        for (int j = 0; j < 4; j++) {
            const unsigned long long* wp = sw + (oc0 + j) * 10;
            ulonglong2 wa = *(const ulonglong2*)(wp);
            ulonglong2 wb = *(const ulonglong2*)(wp + 2);
            ulonglong2 wc = *(const ulonglong2*)(wp + 4);
            ulonglong2 wd = *(const ulonglong2*)(wp + 6);
            unsigned long long w8 = wp[8];

            int a0 = __popcll(nb[0] ^ wa.x) + __popcll(nb[1] ^ wa.y)
                   + __popcll(nb[2] ^ wb.x) + __popcll(nb[3] ^ wb.y)
                   + __popcll(nb[4] ^ wc.x) + __popcll(nb[5] ^ wc.y)
                   + __popcll(nb[6] ^ wd.x) + __popcll(nb[7] ^ wd.y)
                   + __popcll(nb[8] ^ w8);
            int a1 = __popcll(nb[3] ^ wa.x) + __popcll(nb[4] ^ wa.y)
                   + __popcll(nb[5] ^ wb.x) + __popcll(nb[6] ^ wb.y)
                   + __popcll(nb[7] ^ wc.x) + __popcll(nb[8] ^ wc.y)
                   + __popcll(nb[9] ^ wd.x) + __popcll(nb[10] ^ wd.y)
                   + __popcll(nb[11] ^ w8);

            int c0 = 0, c1 = 0;
            if (edge) {
                unsigned long long s = stab[oc0 + j];
                int WR0 = (int)(s & 0xFF),         WR2 = (int)((s >> 8)  & 0xFF);
                int WC0 = (int)((s >> 16) & 0xFF), WC2 = (int)((s >> 24) & 0xFF);
                int p00 = (int)((s >> 32) & 0xFF), p02 = (int)((s >> 40) & 0xFF);
                int p20 = (int)((s >> 48) & 0xFF), p22 = (int)((s >> 56) & 0xFF);
                c0 = t0 * WR0 + lf * WC0 + rt * WC2 - (t0 & lf) * p00 - (t0 & rt) * p02;
                c1 = bo * WR2 + lf * WC0 + rt * WC2 - (bo & lf) * p20 - (bo & rt) * p22;
            }
            d0[j] = base0 - 2 * (a0 - c0);
            d1[j] = base1 - 2 * (a1 - c1);
        }

        // Phase 3: epilogue + stores
        #pragma unroll
        for (int j = 0; j < 4; j++) {
            const int oc = oc0 + j;
            float4 P = spar[oc];              // {ALPHA*scale, bA, aP, bB}
            float o0 = fmaf(P.x, (float)d0[j], r0[j]);
            float u0 = o0 + P.y;
            o0 = (u0 >= 0.f ? u0 : P.z * u0) + P.w;
            float o1 = fmaf(P.x, (float)d1[j], r1[j]);
            float u1 = o1 + P.y;
            o1 = (u1 >= 0.f ? u1 : P.z * u1) + P.w;
            op0[oc * HW]      = o0;
            op0[oc * HW + Wn] = o1;
            if (STAGE == 1) {
                pk0 |= (unsigned long long)(o0 + sK[oc] >= 0.f) << oc;
                pk1 |= (unsigned long long)(o1 + sK[oc] >= 0.f) << oc;
            }
        }
    }
    if (STAGE == 1) {
        g_bits2[(size_t)b * HW + base]      = pk0;
        g_bits2[(size_t)b * HW + base + Wn] = pk1;
    }
}

__global__ void __launch_bounds__(256, 3)
conv1_kernel(const float* __restrict__ x)
{
    conv_body<1>(x, g_out1);
}

__global__ void __launch_bounds__(256, 3)
conv2_kernel(float* __restrict__ out)
{
    conv_body<2>(g_out1, out);
}

// ---------------------------------------------------------------------------
extern "C" void kernel_launch(void* const* d_in, const int* in_sizes, int n_in,
                              void* d_out, int out_size)
{
    const float* x   = (const float*)d_in[0];
    const float* w3  = (const float*)d_in[1];
    const float* wpw = (const float*)d_in[2];
    const float* b11 = (const float*)d_in[3];
    const float* b12 = (const float*)d_in[4];
    const float* b13 = (const float*)d_in[5];
    const float* b21 = (const float*)d_in[6];
    const float* b22 = (const float*)d_in[7];
    const float* b23 = (const float*)d_in[8];
    const float* a1  = (const float*)d_in[9];
    const float* a2  = (const float*)d_in[10];
    float* out = (float*)d_out;

    prep_weights<<<1, 128>>>(w3, wpw, b12, a1, b13, b22, a2, b23, b21);
    pack1_kernel<<<(BHW / 4 + 255) / 256, 256>>>(x, b11);
    conv1_kernel<<<(PAIRS + 255) / 256, 256>>>(x);
    conv2_kernel<<<(PAIRS + 255) / 256, 256>>>(out);
}

// round 5
// speedup vs baseline: 1.0112x; 1.0112x over previous
#include <cuda_runtime.h>

// Problem constants
#define Bn 32
#define Cn 64
#define Hn 112
#define Wn 112
static constexpr int HW    = Hn * Wn;        // 12544
static constexpr int BHW   = Bn * HW;        // 401408
static constexpr int TOTAL = Bn * Cn * HW;   // 25690112
static constexpr float ALPHA = 0.25f;

// Scratch (no cudaMalloc allowed)
__device__ unsigned long long g_bits1[BHW];
__device__ unsigned long long g_bits2[BHW];
__device__ float g_out1[TOTAL];              // ~103 MB .bss

// All per-channel parameters packed into ONE block, staged in global by the
// prep kernel, then copied (one capturable D2D memcpy) into __constant__.
struct CParams {
    unsigned long long w[2][Cn][10];   // packed sign words (tap 0..8) + pad
    unsigned long long tab[2][Cn];     // byte-packed boundary popc corrections
    float4 par[2][Cn];                 // {ALPHA*scale, bA, aP, bB}
    float  k1[Cn];                     // b21 (stage-1 repack bias)
};
__device__   CParams g_cb;   // staging (written by prep kernel)
__constant__ CParams c_cb;   // read by conv kernels (LDCU/uniform path)

// ---------------------------------------------------------------------------
// K0: weight prep. scale = mean|w|; pack sign bits (w>=0 -> bit 1); build
// per-oc boundary correction table (popc sums of weight rows/cols/corners):
//   byte 0=row0  1=row2  2=col0  3=col2  4=p(0,0) 5=p(0,2) 6=p(2,0) 7=p(2,2)
// ---------------------------------------------------------------------------
__global__ void prep_weights(const float* __restrict__ w3,
                             const float* __restrict__ wpw,
                             const float* __restrict__ b12,
                             const float* __restrict__ a1,
                             const float* __restrict__ b13,
                             const float* __restrict__ b22,
                             const float* __restrict__ a2,
                             const float* __restrict__ b23,
                             const float* __restrict__ b21)
{
    int t = threadIdx.x;            // 0..127
    int set = t >> 6;               // 0 = w3, 1 = w_pw
    int oc  = t & 63;
    const float* w = set ? wpw : w3;
    float s = 0.f;
    unsigned long long wd[9];
    #pragma unroll
    for (int tap = 0; tap < 9; tap++) {
        unsigned long long word = 0ull;
        for (int ic = 0; ic < 64; ic++) {
            float v = w[(oc * 64 + ic) * 9 + tap];
            s += fabsf(v);
            word |= (unsigned long long)(v >= 0.f) << ic;
        }
        wd[tap] = word;
        g_cb.w[set][oc][tap] = word;
    }
    g_cb.w[set][oc][9] = 0ull;
    float scale = s * (1.f / 576.f);

    unsigned long long pc[9];
    #pragma unroll
    for (int tap = 0; tap < 9; tap++) pc[tap] = (unsigned long long)__popcll(wd[tap]);
    unsigned long long tab = 0;
    tab |= (pc[0] + pc[1] + pc[2]);         // row0
    tab |= (pc[6] + pc[7] + pc[8]) << 8;    // row2
    tab |= (pc[0] + pc[3] + pc[6]) << 16;   // col0
    tab |= (pc[2] + pc[5] + pc[8]) << 24;   // col2
    tab |= pc[0] << 32;                     // corners
    tab |= pc[2] << 40;
    tab |= pc[6] << 48;
    tab |= pc[8] << 56;
    g_cb.tab[set][oc] = tab;

    if (set == 0) {
        g_cb.par[0][oc] = make_float4(ALPHA * scale, b12[oc], a1[oc], b13[oc]);
        g_cb.k1[oc] = b21[oc];
    } else {
        g_cb.par[1][oc] = make_float4(ALPHA * scale, b22[oc], a2[oc], b23[oc]);
    }
}

// ---------------------------------------------------------------------------
// K1: pack1 — 4 pixels/thread, LDG.128 reads + STG.128 writes.
// bits1[pix] = bitpack over c of (x + b11[c] >= 0).
// ---------------------------------------------------------------------------
__global__ void pack1_kernel(const float* __restrict__ x,
                             const float* __restrict__ b11)
{
    __shared__ float sb[64];
    if (threadIdx.x < 64) sb[threadIdx.x] = b11[threadIdx.x];
    __syncthreads();

    int t = blockIdx.x * blockDim.x + threadIdx.x;
    if (t >= BHW / 4) return;
    int b = t / (HW / 4);
    int hw = (t - b * (HW / 4)) * 4;
    const float4* xp = (const float4*)(x + (size_t)b * Cn * HW + hw);

    unsigned long long w0 = 0, w1 = 0, w2 = 0, w3v = 0;
    #pragma unroll 8
    for (int c = 0; c < 64; c++) {
        float4 v = __ldg(&xp[c * (HW / 4)]);
        float bc = sb[c];
        w0  |= (unsigned long long)(v.x + bc >= 0.f) << c;
        w1  |= (unsigned long long)(v.y + bc >= 0.f) << c;
        w2  |= (unsigned long long)(v.z + bc >= 0.f) << c;
        w3v |= (unsigned long long)(v.w + bc >= 0.f) << c;
    }
    ulonglong2* dst = (ulonglong2*)(g_bits1 + (size_t)b * HW + hw);
    dst[0] = make_ulonglong2(w0, w1);
    dst[1] = make_ulonglong2(w2, w3v);
}

// ---------------------------------------------------------------------------
// Binary conv + fused epilogue. 1 pixel/thread; FULLY UNROLLED oc loop so
// every weight/param access is an immediate-offset __constant__ load ->
// LDCU into uniform registers (no LDS, no crossbar, LOP3 takes UR operands).
// OOB taps read as 0 and the over-count is corrected (edge threads only)
// via the per-oc byte table.
// ---------------------------------------------------------------------------
template <int STAGE>
__device__ __forceinline__ void conv_body(const float* __restrict__ resid,
                                          float* __restrict__ outp)
{
    int pix = blockIdx.x * blockDim.x + threadIdx.x;
    if (pix >= BHW) return;
    int b = pix / HW, hw = pix - b * HW;
    int y = hw / Wn, x = hw - y * Wn;

    const int t0 = (y == 0);
    const int bo = (y == Hn - 1);
    const int lf = (x == 0);
    const int rt = (x == Wn - 1);
    const bool edge = (t0 | bo | lf | rt) != 0;

    const unsigned long long* bp =
        ((STAGE == 1) ? g_bits1 : g_bits2) + (size_t)b * HW;

    // 3x3 neighborhood; OOB words read as 0 (over-count corrected later)
    unsigned long long nb[9];
    #pragma unroll
    for (int rr = 0; rr < 3; rr++) {
        bool rok = (rr == 0) ? !t0 : (rr == 2) ? !bo : true;
        int rb = hw + (rr - 1) * Wn;
        nb[rr * 3 + 0] = (rok && !lf) ? bp[rb - 1] : 0ull;
        nb[rr * 3 + 1] =  rok         ? bp[rb]     : 0ull;
        nb[rr * 3 + 2] = (rok && !rt) ? bp[rb + 1] : 0ull;
    }
    const int basei = 64 * (3 - t0 - bo) * (3 - lf - rt);

    const float* rp = resid + (size_t)b * Cn * HW + hw;
    float*       op = outp  + (size_t)b * Cn * HW + hw;

    unsigned long long pk = 0ull;

    #pragma unroll
    for (int c8 = 0; c8 < 8; c8++) {
        const int oc0 = c8 * 8;

        // batched residual loads (MLP = 8)
        float r[8];
        #pragma unroll
        for (int j = 0; j < 8; j++)
            r[j] = rp[(oc0 + j) * HW];

        #pragma unroll
        for (int j = 0; j < 8; j++) {
            const int oc = oc0 + j;
            const unsigned long long* wp = c_cb.w[STAGE - 1][oc];

            int a = 0;
            #pragma unroll
            for (int t = 0; t < 9; t++)
                a += __popcll(nb[t] ^ wp[t]);

            int corr = 0;
            if (edge) {
                unsigned long long s = c_cb.tab[STAGE - 1][oc];
                int WR0 = (int)(s & 0xFF),         WR2 = (int)((s >> 8)  & 0xFF);
                int WC0 = (int)((s >> 16) & 0xFF), WC2 = (int)((s >> 24) & 0xFF);
                int p00 = (int)((s >> 32) & 0xFF), p02 = (int)((s >> 40) & 0xFF);
                int p20 = (int)((s >> 48) & 0xFF), p22 = (int)((s >> 56) & 0xFF);
                corr = t0 * WR0 + bo * WR2 + lf * WC0 + rt * WC2
                     - (t0 & lf) * p00 - (t0 & rt) * p02
                     - (bo & lf) * p20 - (bo & rt) * p22;
            }
            int d = basei - 2 * (a - corr);

            float4 P = c_cb.par[STAGE - 1][oc];   // {ALPHA*scale, bA, aP, bB}
            float o = fmaf(P.x, (float)d, r[j]);
            float u = o + P.y;
            o = (u >= 0.f ? u : P.z * u) + P.w;
            op[oc * HW] = o;
            if (STAGE == 1)
                pk |= (unsigned long long)(o + c_cb.k1[oc] >= 0.f) << oc;
        }
    }
    if (STAGE == 1) g_bits2[pix] = pk;
}

__global__ void __launch_bounds__(256, 4)
conv1_kernel(const float* __restrict__ x)
{
    conv_body<1>(x, g_out1);
}

__global__ void __launch_bounds__(256, 4)
conv2_kernel(float* __restrict__ out)
{
    conv_body<2>(g_out1, out);
}

// ---------------------------------------------------------------------------
extern "C" void kernel_launch(void* const* d_in, const int* in_sizes, int n_in,
                              void* d_out, int out_size)
{
    const float* x   = (const float*)d_in[0];
    const float* w3  = (const float*)d_in[1];
    const float* wpw = (const float*)d_in[2];
    const float* b11 = (const float*)d_in[3];
    const float* b12 = (const float*)d_in[4];
    const float* b13 = (const float*)d_in[5];
    const float* b21 = (const float*)d_in[6];
    const float* b22 = (const float*)d_in[7];
    const float* b23 = (const float*)d_in[8];
    const float* a1  = (const float*)d_in[9];
    const float* a2  = (const float*)d_in[10];
    float* out = (float*)d_out;

    // Addresses of staging + constant blocks (pure queries, capture-safe)
    void *p_stage = nullptr, *p_const = nullptr;
    cudaGetSymbolAddress(&p_stage, g_cb);
    cudaGetSymbolAddress(&p_const, c_cb);

    prep_weights<<<1, 128>>>(w3, wpw, b12, a1, b13, b22, a2, b23, b21);
    cudaMemcpyAsync(p_const, p_stage, sizeof(CParams), cudaMemcpyDeviceToDevice);
    pack1_kernel<<<(BHW / 4 + 255) / 256, 256>>>(x, b11);
    conv1_kernel<<<(BHW + 255) / 256, 256>>>(x);
    conv2_kernel<<<(BHW + 255) / 256, 256>>>(out);
}